// round 1
// baseline (speedup 1.0000x reference)
#include <cuda_runtime.h>
#include <math.h>

#define BB 2
#define SS 2048
#define EE 1024
#define HH 16
#define DD 64
#define MM (BB*SS)

// Scratch (static device globals; no runtime allocation)
__device__ float g_q[BB*HH*SS*DD];      // 16 MB
__device__ float g_k[BB*HH*SS*DD];      // 16 MB
__device__ float g_v[BB*HH*SS*DD];      // 16 MB (pre-masked)
__device__ float g_vmean[BB*HH*DD];
__device__ float g_ao[BB*SS*EE];        // 16 MB, layout [B,S,H,D] == [B,S,E]
__device__ float g_active[HH];

// ---------------------------------------------------------------------------
// Head mask: active[h] = sigmoid(gates[h]*imp[h]) > thr
// ---------------------------------------------------------------------------
__global__ void mask_kernel(const float* __restrict__ gates,
                            const float* __restrict__ imp,
                            const float* __restrict__ thr) {
    int h = threadIdx.x;
    if (h < HH) {
        float z  = gates[h] * imp[h];
        float gs = 1.0f / (1.0f + expf(-z));
        g_active[h] = (gs > thr[0]) ? 1.0f : 0.0f;
    }
}

// ---------------------------------------------------------------------------
// QKV GEMM: Y[m,n] = sum_k X[m,k] * W[n,k] + b[n], scatter to q/k/v [B,H,S,D]
// BM=BN=64, BK=16, 256 threads, 4x4 per thread
// ---------------------------------------------------------------------------
__global__ void __launch_bounds__(256) qkv_gemm_kernel(
    const float* __restrict__ X,
    const float* __restrict__ W,
    const float* __restrict__ bias) {
    __shared__ float As[16][64];
    __shared__ float Bs[16][64];
    const int tid = threadIdx.x;
    const int m0 = blockIdx.y * 64;
    const int n0 = blockIdx.x * 64;
    const int ty = tid >> 4, tx = tid & 15;
    const int lr = tid >> 2;          // 0..63
    const int lk = (tid & 3) << 2;    // 0,4,8,12
    float c[4][4] = {};

    for (int k0 = 0; k0 < EE; k0 += 16) {
        float4 av = *(const float4*)(X + (size_t)(m0 + lr) * EE + k0 + lk);
        float4 bv = *(const float4*)(W + (size_t)(n0 + lr) * EE + k0 + lk);
        As[lk+0][lr] = av.x; As[lk+1][lr] = av.y; As[lk+2][lr] = av.z; As[lk+3][lr] = av.w;
        Bs[lk+0][lr] = bv.x; Bs[lk+1][lr] = bv.y; Bs[lk+2][lr] = bv.z; Bs[lk+3][lr] = bv.w;
        __syncthreads();
#pragma unroll
        for (int kk = 0; kk < 16; kk++) {
            float4 a = *(const float4*)&As[kk][ty * 4];
            float4 b = *(const float4*)&Bs[kk][tx * 4];
            float aa[4] = {a.x, a.y, a.z, a.w};
            float bb[4] = {b.x, b.y, b.z, b.w};
#pragma unroll
            for (int i = 0; i < 4; i++)
#pragma unroll
                for (int j = 0; j < 4; j++)
                    c[i][j] += aa[i] * bb[j];
        }
        __syncthreads();
    }

#pragma unroll
    for (int i = 0; i < 4; i++) {
        int m = m0 + ty * 4 + i;
        int bI = m >> 11;           // /2048
        int s  = m & (SS - 1);
#pragma unroll
        for (int j = 0; j < 4; j++) {
            int n = n0 + tx * 4 + j;
            float val = c[i][j] + bias[n];
            int cc  = n >> 10;      // 0=q 1=k 2=v
            int rem = n & 1023;
            int h = rem >> 6, d = rem & 63;
            size_t off = (((size_t)(bI * HH + h)) * SS + s) * DD + d;
            if (cc == 0)      g_q[off] = val;
            else if (cc == 1) g_k[off] = val;
            else              g_v[off] = val * g_active[h];
        }
    }
}

// ---------------------------------------------------------------------------
// vmean[b,h,d] = mean_s v[b,h,s,d]
// ---------------------------------------------------------------------------
__global__ void vmean_kernel() {
    int bh = blockIdx.x;            // 0..BB*HH-1
    int d = threadIdx.x & 63;
    int chunk = threadIdx.x >> 6;   // 0..3
    size_t base = (size_t)bh * SS * DD;
    float sum = 0.f;
    for (int s = chunk * 512; s < (chunk + 1) * 512; s++)
        sum += g_v[base + (size_t)s * DD + d];
    __shared__ float red[256];
    red[threadIdx.x] = sum;
    __syncthreads();
    if (chunk == 0) {
        float t = red[d] + red[64 + d] + red[128 + d] + red[192 + d];
        g_vmean[bh * DD + d] = t * (1.0f / SS);
    }
}

// ---------------------------------------------------------------------------
// Flash attention per (b,h,qtile). BQ=64, BKT=64, 256 threads (4 per row).
// Q row in registers. P tile aliases the K smem buffer.
// ---------------------------------------------------------------------------
__global__ void __launch_bounds__(256) attn_kernel() {
    __shared__ float KsPs[64][68];  // K tile, then reused as P tile
    __shared__ float Vs[64][68];
    const int tid = threadIdx.x;
    const int r  = tid >> 2;        // 0..63 query row within tile
    const int qd = tid & 3;         // quad lane
    const int b = blockIdx.z, h = blockIdx.y;
    const int q0 = blockIdx.x * 64;
    const size_t bh = (size_t)(b * HH + h) * SS * DD;

    // Q row (all 4 quad threads hold the full 64-d row)
    float qreg[64];
    {
        const float4* qp = (const float4*)(g_q + bh + (size_t)(q0 + r) * DD);
#pragma unroll
        for (int i = 0; i < 16; i++) {
            float4 t = qp[i];
            qreg[4*i+0] = t.x; qreg[4*i+1] = t.y; qreg[4*i+2] = t.z; qreg[4*i+3] = t.w;
        }
    }

    float m_i = -1e30f, l_i = 0.f;
    float acc[16];
#pragma unroll
    for (int i = 0; i < 16; i++) acc[i] = 0.f;

    const int lr = tid >> 2;
    const int lc = (tid & 3) * 16;

    for (int kt = 0; kt < SS; kt += 64) {
        // load K,V tiles (64x64 each)
        const float4* kp = (const float4*)(g_k + bh + (size_t)(kt + lr) * DD + lc);
        const float4* vp = (const float4*)(g_v + bh + (size_t)(kt + lr) * DD + lc);
#pragma unroll
        for (int i = 0; i < 4; i++) {
            *(float4*)&KsPs[lr][lc + 4 * i] = kp[i];
            *(float4*)&Vs[lr][lc + 4 * i]   = vp[i];
        }
        __syncthreads();

        // scores for this thread's 16 columns: j = jj*4 + qd (interleaved)
        float sv[16];
#pragma unroll
        for (int jj = 0; jj < 16; jj++) {
            int j = jj * 4 + qd;
            float a0 = 0.f, a1 = 0.f, a2 = 0.f, a3 = 0.f;
#pragma unroll
            for (int d4 = 0; d4 < 16; d4++) {
                float4 kv = *(const float4*)&KsPs[j][d4 * 4];
                a0 += qreg[d4*4+0] * kv.x;
                a1 += qreg[d4*4+1] * kv.y;
                a2 += qreg[d4*4+2] * kv.z;
                a3 += qreg[d4*4+3] * kv.w;
            }
            sv[jj] = (a0 + a1) + (a2 + a3);
        }

        // online softmax (row stats across the 4-thread quad)
        float mloc = sv[0];
#pragma unroll
        for (int jj = 1; jj < 16; jj++) mloc = fmaxf(mloc, sv[jj]);
        mloc = fmaxf(mloc, __shfl_xor_sync(0xffffffffu, mloc, 1));
        mloc = fmaxf(mloc, __shfl_xor_sync(0xffffffffu, mloc, 2));
        float m_new = fmaxf(m_i, mloc);
        float scale = __expf(m_i - m_new);

        float pr[16];
        float psum = 0.f;
#pragma unroll
        for (int jj = 0; jj < 16; jj++) {
            pr[jj] = __expf(sv[jj] - m_new);
            psum += pr[jj];
        }
        psum += __shfl_xor_sync(0xffffffffu, psum, 1);
        psum += __shfl_xor_sync(0xffffffffu, psum, 2);
        l_i = l_i * scale + psum;
        m_i = m_new;
#pragma unroll
        for (int i = 0; i < 16; i++) acc[i] *= scale;

        // done reading K everywhere -> P may overwrite the K buffer
        __syncthreads();
#pragma unroll
        for (int jj = 0; jj < 16; jj++)
            KsPs[r][jj * 4 + qd] = pr[jj];
        __syncwarp();   // P row is produced by this warp's own quad

        // acc[d-slice] += P[r,:] @ V[:, d-slice],  d-slice = qd*16 + [0,16)
#pragma unroll 4
        for (int j = 0; j < 64; j++) {
            float p = KsPs[r][j];
#pragma unroll
            for (int i4 = 0; i4 < 4; i4++) {
                float4 vv = *(const float4*)&Vs[j][qd * 16 + i4 * 4];
                acc[i4*4+0] += p * vv.x;
                acc[i4*4+1] += p * vv.y;
                acc[i4*4+2] += p * vv.z;
                acc[i4*4+3] += p * vv.w;
            }
        }
        __syncthreads();   // before next tile overwrites KsPs/Vs
    }

    // epilogue: normalize + add vmean, write [B,S,H,D]
    float inv_l = 1.0f / l_i;
    const float* vm = g_vmean + (size_t)(b * HH + h) * DD + qd * 16;
    float* outp = g_ao + ((size_t)(b * SS + q0 + r) * HH + h) * DD + qd * 16;
#pragma unroll
    for (int i4 = 0; i4 < 4; i4++) {
        float4 o;
        o.x = acc[i4*4+0] * inv_l + vm[i4*4+0];
        o.y = acc[i4*4+1] * inv_l + vm[i4*4+1];
        o.z = acc[i4*4+2] * inv_l + vm[i4*4+2];
        o.w = acc[i4*4+3] * inv_l + vm[i4*4+3];
        *(float4*)(outp + i4 * 4) = o;
    }
}

// ---------------------------------------------------------------------------
// Output GEMM: Y[m,e] = sum_k ao[m,k] * out_w[e,k] + out_b[e]
// ---------------------------------------------------------------------------
__global__ void __launch_bounds__(256) out_gemm_kernel(
    const float* __restrict__ W,
    const float* __restrict__ bias,
    float* __restrict__ Y) {
    __shared__ float As[16][64];
    __shared__ float Bs[16][64];
    const int tid = threadIdx.x;
    const int m0 = blockIdx.y * 64;
    const int n0 = blockIdx.x * 64;
    const int ty = tid >> 4, tx = tid & 15;
    const int lr = tid >> 2;
    const int lk = (tid & 3) << 2;
    float c[4][4] = {};

    for (int k0 = 0; k0 < EE; k0 += 16) {
        float4 av = *(const float4*)(g_ao + (size_t)(m0 + lr) * EE + k0 + lk);
        float4 bv = *(const float4*)(W + (size_t)(n0 + lr) * EE + k0 + lk);
        As[lk+0][lr] = av.x; As[lk+1][lr] = av.y; As[lk+2][lr] = av.z; As[lk+3][lr] = av.w;
        Bs[lk+0][lr] = bv.x; Bs[lk+1][lr] = bv.y; Bs[lk+2][lr] = bv.z; Bs[lk+3][lr] = bv.w;
        __syncthreads();
#pragma unroll
        for (int kk = 0; kk < 16; kk++) {
            float4 a = *(const float4*)&As[kk][ty * 4];
            float4 b = *(const float4*)&Bs[kk][tx * 4];
            float aa[4] = {a.x, a.y, a.z, a.w};
            float bb[4] = {b.x, b.y, b.z, b.w};
#pragma unroll
            for (int i = 0; i < 4; i++)
#pragma unroll
                for (int j = 0; j < 4; j++)
                    c[i][j] += aa[i] * bb[j];
        }
        __syncthreads();
    }

#pragma unroll
    for (int i = 0; i < 4; i++) {
        int m = m0 + ty * 4 + i;
#pragma unroll
        for (int j = 0; j < 4; j++) {
            int n = n0 + tx * 4 + j;
            Y[(size_t)m * EE + n] = c[i][j] + bias[n];
        }
    }
}

// ---------------------------------------------------------------------------
extern "C" void kernel_launch(void* const* d_in, const int* in_sizes, int n_in,
                              void* d_out, int out_size) {
    const float* x      = (const float*)d_in[0];
    const float* qkv_w  = (const float*)d_in[1];
    const float* qkv_b  = (const float*)d_in[2];
    const float* out_w  = (const float*)d_in[3];
    const float* out_b  = (const float*)d_in[4];
    const float* gates  = (const float*)d_in[5];
    const float* imp    = (const float*)d_in[6];
    const float* thr    = (const float*)d_in[7];
    float* out = (float*)d_out;

    mask_kernel<<<1, 32>>>(gates, imp, thr);

    dim3 g1(3 * EE / 64, MM / 64);          // 48 x 64
    qkv_gemm_kernel<<<g1, 256>>>(x, qkv_w, qkv_b);

    vmean_kernel<<<BB * HH, 256>>>();

    dim3 g2(SS / 64, HH, BB);               // 32 x 16 x 2
    attn_kernel<<<g2, 256>>>();

    dim3 g3(EE / 64, MM / 64);              // 16 x 64
    out_gemm_kernel<<<g3, 256>>>(out_w, out_b, out);
}

// round 2
// speedup vs baseline: 1.1832x; 1.1832x over previous
#include <cuda_runtime.h>
#include <math.h>

#define BB 2
#define SS 2048
#define EE 1024
#define HH 16
#define DD 64
#define MM (BB*SS)

// Scratch (static device globals; no runtime allocation)
__device__ float g_q[BB*HH*SS*DD];      // 16 MB
__device__ float g_k[BB*HH*SS*DD];      // 16 MB
__device__ float g_v[BB*HH*SS*DD];      // 16 MB (pre-masked)
__device__ float g_vmean[BB*HH*DD];
__device__ float g_ao[BB*SS*EE];        // 16 MB, layout [B,S,H,D] == [B,S,E]
__device__ float g_active[HH];

// ---------------------------------------------------------------------------
// helpers: tf32 convert + mma.sync m16n8k8
// ---------------------------------------------------------------------------
__device__ __forceinline__ unsigned f2tf32(float x) {
    unsigned r;
    asm("cvt.rna.tf32.f32 %0, %1;" : "=r"(r) : "f"(x));
    return r;
}

__device__ __forceinline__ void mma_tf32(float c[4], const unsigned a[4], const unsigned b[2]) {
    asm volatile(
        "mma.sync.aligned.m16n8k8.row.col.f32.tf32.tf32.f32 "
        "{%0,%1,%2,%3}, {%4,%5,%6,%7}, {%8,%9}, {%0,%1,%2,%3};"
        : "+f"(c[0]), "+f"(c[1]), "+f"(c[2]), "+f"(c[3])
        : "r"(a[0]), "r"(a[1]), "r"(a[2]), "r"(a[3]),
          "r"(b[0]), "r"(b[1]));
}

// ---------------------------------------------------------------------------
// Head mask: active[h] = sigmoid(gates[h]*imp[h]) > thr
// ---------------------------------------------------------------------------
__global__ void mask_kernel(const float* __restrict__ gates,
                            const float* __restrict__ imp,
                            const float* __restrict__ thr) {
    int h = threadIdx.x;
    if (h < HH) {
        float z  = gates[h] * imp[h];
        float gs = 1.0f / (1.0f + expf(-z));
        g_active[h] = (gs > thr[0]) ? 1.0f : 0.0f;
    }
}

// ---------------------------------------------------------------------------
// TF32 tensor-core GEMM: C[m,n] = sum_k A[m,k]*B[n,k] + bias[n]
// BM=BN=128, BK=32, 256 threads (8 warps, 2x4), warp tile 64x32.
// MODE 0: qkv epilogue (scatter to g_q/g_k/g_v). MODE 1: write Y row-major.
// Smem row stride 36 words -> fragment LDS bank = (4m+k)%32, conflict-free.
// ---------------------------------------------------------------------------
template <int MODE>
__global__ void __launch_bounds__(256, 1) gemm_tf32_kernel(
    const float* __restrict__ A,
    const float* __restrict__ B,
    const float* __restrict__ bias,
    float* __restrict__ Y) {
    __shared__ unsigned As[128][36];
    __shared__ unsigned Bs[128][36];

    const int tid  = threadIdx.x;
    const int lane = tid & 31;
    const int warp = tid >> 5;
    const int wm = (warp >> 2) * 64;   // warp row offset in block tile
    const int wn = (warp & 3) * 32;    // warp col offset
    const int m0 = blockIdx.y * 128;
    const int n0 = blockIdx.x * 128;
    const int grp = lane >> 2;         // 0..7
    const int tig = lane & 3;          // 0..3

    // g2s mapping: each thread loads one 16-float half-row of A and of B
    const int grow = tid >> 1;             // 0..127
    const int gk   = (tid & 1) * 16;       // 0 or 16
    const float* Aptr = A + (size_t)(m0 + grow) * EE + gk;
    const float* Bptr = B + (size_t)(n0 + grow) * EE + gk;

    float acc[4][4][4];
#pragma unroll
    for (int i = 0; i < 4; i++)
#pragma unroll
        for (int j = 0; j < 4; j++)
#pragma unroll
            for (int r = 0; r < 4; r++) acc[i][j][r] = 0.f;

    float4 pa[4], pb[4];
#pragma unroll
    for (int i = 0; i < 4; i++) {
        pa[i] = *(const float4*)(Aptr + 4 * i);
        pb[i] = *(const float4*)(Bptr + 4 * i);
    }

    const int NT = EE / 32;  // 32 k-tiles
    for (int kt = 0; kt < NT; kt++) {
        // store prefetched tile (converted to tf32 bits)
#pragma unroll
        for (int i = 0; i < 4; i++) {
            uint4 ua, ub;
            ua.x = f2tf32(pa[i].x); ua.y = f2tf32(pa[i].y);
            ua.z = f2tf32(pa[i].z); ua.w = f2tf32(pa[i].w);
            ub.x = f2tf32(pb[i].x); ub.y = f2tf32(pb[i].y);
            ub.z = f2tf32(pb[i].z); ub.w = f2tf32(pb[i].w);
            *(uint4*)&As[grow][gk + 4 * i] = ua;
            *(uint4*)&Bs[grow][gk + 4 * i] = ub;
        }
        __syncthreads();

        // prefetch next tile while computing
        if (kt + 1 < NT) {
            const float* An = Aptr + (kt + 1) * 32;
            const float* Bn = Bptr + (kt + 1) * 32;
#pragma unroll
            for (int i = 0; i < 4; i++) {
                pa[i] = *(const float4*)(An + 4 * i);
                pb[i] = *(const float4*)(Bn + 4 * i);
            }
        }

        // compute: 4 k-steps of 8
#pragma unroll
        for (int ks = 0; ks < 4; ks++) {
            const int kq = ks * 8 + tig;
            unsigned a[4][4];
#pragma unroll
            for (int mi = 0; mi < 4; mi++) {
                const int mr = wm + mi * 16 + grp;
                a[mi][0] = As[mr][kq];
                a[mi][1] = As[mr + 8][kq];
                a[mi][2] = As[mr][kq + 4];
                a[mi][3] = As[mr + 8][kq + 4];
            }
            unsigned b[4][2];
#pragma unroll
            for (int ni = 0; ni < 4; ni++) {
                const int nr = wn + ni * 8 + grp;
                b[ni][0] = Bs[nr][kq];
                b[ni][1] = Bs[nr][kq + 4];
            }
#pragma unroll
            for (int mi = 0; mi < 4; mi++)
#pragma unroll
                for (int ni = 0; ni < 4; ni++)
                    mma_tf32(acc[mi][ni], a[mi], b[ni]);
        }
        __syncthreads();
    }

    // epilogue
#pragma unroll
    for (int mi = 0; mi < 4; mi++) {
        const int rbase = m0 + wm + mi * 16 + grp;
#pragma unroll
        for (int ni = 0; ni < 4; ni++) {
            const int j = n0 + wn + ni * 8 + 2 * tig;   // even col, pair (j, j+1)
            const float b0 = bias[j], b1 = bias[j + 1];
#pragma unroll
            for (int rh = 0; rh < 2; rh++) {
                const int m = rbase + rh * 8;
                const float v0 = acc[mi][ni][rh * 2 + 0] + b0;
                const float v1 = acc[mi][ni][rh * 2 + 1] + b1;
                if (MODE == 1) {
                    float2 o; o.x = v0; o.y = v1;
                    *(float2*)(Y + (size_t)m * EE + j) = o;
                } else {
                    // qkv scatter: n in [0,3072): cc*1024 + h*64 + d
                    const int cc  = j >> 10;
                    const int rem = j & 1023;
                    const int h = rem >> 6, d = rem & 63;
                    const int bI = m >> 11;
                    const int s  = m & (SS - 1);
                    const size_t off = (((size_t)(bI * HH + h)) * SS + s) * DD + d;
                    float2 o;
                    if (cc == 0) {
                        o.x = v0; o.y = v1;
                        *(float2*)(g_q + off) = o;
                    } else if (cc == 1) {
                        o.x = v0; o.y = v1;
                        *(float2*)(g_k + off) = o;
                    } else {
                        const float am = g_active[h];
                        o.x = v0 * am; o.y = v1 * am;
                        *(float2*)(g_v + off) = o;
                    }
                }
            }
        }
    }
}

// ---------------------------------------------------------------------------
// vmean[b,h,d] = mean_s v[b,h,s,d]
// ---------------------------------------------------------------------------
__global__ void vmean_kernel() {
    int bh = blockIdx.x;            // 0..BB*HH-1
    int d = threadIdx.x & 63;
    int chunk = threadIdx.x >> 6;   // 0..3
    size_t base = (size_t)bh * SS * DD;
    float sum = 0.f;
    for (int s = chunk * 512; s < (chunk + 1) * 512; s++)
        sum += g_v[base + (size_t)s * DD + d];
    __shared__ float red[256];
    red[threadIdx.x] = sum;
    __syncthreads();
    if (chunk == 0) {
        float t = red[d] + red[64 + d] + red[128 + d] + red[192 + d];
        g_vmean[bh * DD + d] = t * (1.0f / SS);
    }
}

// ---------------------------------------------------------------------------
// Flash attention per (b,h,qtile). BQ=64, BKT=64, 256 threads (4 per row).
// Q row in registers. P tile aliases the K smem buffer. (unchanged)
// ---------------------------------------------------------------------------
__global__ void __launch_bounds__(256) attn_kernel() {
    __shared__ float KsPs[64][68];  // K tile, then reused as P tile
    __shared__ float Vs[64][68];
    const int tid = threadIdx.x;
    const int r  = tid >> 2;        // 0..63 query row within tile
    const int qd = tid & 3;         // quad lane
    const int b = blockIdx.z, h = blockIdx.y;
    const int q0 = blockIdx.x * 64;
    const size_t bh = (size_t)(b * HH + h) * SS * DD;

    float qreg[64];
    {
        const float4* qp = (const float4*)(g_q + bh + (size_t)(q0 + r) * DD);
#pragma unroll
        for (int i = 0; i < 16; i++) {
            float4 t = qp[i];
            qreg[4*i+0] = t.x; qreg[4*i+1] = t.y; qreg[4*i+2] = t.z; qreg[4*i+3] = t.w;
        }
    }

    float m_i = -1e30f, l_i = 0.f;
    float acc[16];
#pragma unroll
    for (int i = 0; i < 16; i++) acc[i] = 0.f;

    const int lr = tid >> 2;
    const int lc = (tid & 3) * 16;

    for (int kt = 0; kt < SS; kt += 64) {
        const float4* kp = (const float4*)(g_k + bh + (size_t)(kt + lr) * DD + lc);
        const float4* vp = (const float4*)(g_v + bh + (size_t)(kt + lr) * DD + lc);
#pragma unroll
        for (int i = 0; i < 4; i++) {
            *(float4*)&KsPs[lr][lc + 4 * i] = kp[i];
            *(float4*)&Vs[lr][lc + 4 * i]   = vp[i];
        }
        __syncthreads();

        float sv[16];
#pragma unroll
        for (int jj = 0; jj < 16; jj++) {
            int j = jj * 4 + qd;
            float a0 = 0.f, a1 = 0.f, a2 = 0.f, a3 = 0.f;
#pragma unroll
            for (int d4 = 0; d4 < 16; d4++) {
                float4 kv = *(const float4*)&KsPs[j][d4 * 4];
                a0 += qreg[d4*4+0] * kv.x;
                a1 += qreg[d4*4+1] * kv.y;
                a2 += qreg[d4*4+2] * kv.z;
                a3 += qreg[d4*4+3] * kv.w;
            }
            sv[jj] = (a0 + a1) + (a2 + a3);
        }

        float mloc = sv[0];
#pragma unroll
        for (int jj = 1; jj < 16; jj++) mloc = fmaxf(mloc, sv[jj]);
        mloc = fmaxf(mloc, __shfl_xor_sync(0xffffffffu, mloc, 1));
        mloc = fmaxf(mloc, __shfl_xor_sync(0xffffffffu, mloc, 2));
        float m_new = fmaxf(m_i, mloc);
        float scale = __expf(m_i - m_new);

        float pr[16];
        float psum = 0.f;
#pragma unroll
        for (int jj = 0; jj < 16; jj++) {
            pr[jj] = __expf(sv[jj] - m_new);
            psum += pr[jj];
        }
        psum += __shfl_xor_sync(0xffffffffu, psum, 1);
        psum += __shfl_xor_sync(0xffffffffu, psum, 2);
        l_i = l_i * scale + psum;
        m_i = m_new;
#pragma unroll
        for (int i = 0; i < 16; i++) acc[i] *= scale;

        __syncthreads();
#pragma unroll
        for (int jj = 0; jj < 16; jj++)
            KsPs[r][jj * 4 + qd] = pr[jj];
        __syncwarp();

#pragma unroll 4
        for (int j = 0; j < 64; j++) {
            float p = KsPs[r][j];
#pragma unroll
            for (int i4 = 0; i4 < 4; i4++) {
                float4 vv = *(const float4*)&Vs[j][qd * 16 + i4 * 4];
                acc[i4*4+0] += p * vv.x;
                acc[i4*4+1] += p * vv.y;
                acc[i4*4+2] += p * vv.z;
                acc[i4*4+3] += p * vv.w;
            }
        }
        __syncthreads();
    }

    float inv_l = 1.0f / l_i;
    const float* vm = g_vmean + (size_t)(b * HH + h) * DD + qd * 16;
    float* outp = g_ao + ((size_t)(b * SS + q0 + r) * HH + h) * DD + qd * 16;
#pragma unroll
    for (int i4 = 0; i4 < 4; i4++) {
        float4 o;
        o.x = acc[i4*4+0] * inv_l + vm[i4*4+0];
        o.y = acc[i4*4+1] * inv_l + vm[i4*4+1];
        o.z = acc[i4*4+2] * inv_l + vm[i4*4+2];
        o.w = acc[i4*4+3] * inv_l + vm[i4*4+3];
        *(float4*)(outp + i4 * 4) = o;
    }
}

// ---------------------------------------------------------------------------
extern "C" void kernel_launch(void* const* d_in, const int* in_sizes, int n_in,
                              void* d_out, int out_size) {
    const float* x      = (const float*)d_in[0];
    const float* qkv_w  = (const float*)d_in[1];
    const float* qkv_b  = (const float*)d_in[2];
    const float* out_w  = (const float*)d_in[3];
    const float* out_b  = (const float*)d_in[4];
    const float* gates  = (const float*)d_in[5];
    const float* imp    = (const float*)d_in[6];
    const float* thr    = (const float*)d_in[7];
    float* out = (float*)d_out;

    mask_kernel<<<1, 32>>>(gates, imp, thr);

    // QKV projection: [4096,1024] x [3072,1024]^T
    {
        dim3 g(3 * EE / 128, MM / 128);      // 24 x 32
        gemm_tf32_kernel<0><<<g, 256>>>(x, qkv_w, qkv_b, nullptr);
    }

    vmean_kernel<<<BB * HH, 256>>>();

    {
        dim3 g2(SS / 64, HH, BB);            // 32 x 16 x 2
        attn_kernel<<<g2, 256>>>();
    }

    // Output projection: [4096,1024] x [1024,1024]^T
    {
        float* ao;
        cudaGetSymbolAddress((void**)&ao, g_ao);
        dim3 g(EE / 128, MM / 128);          // 8 x 32
        gemm_tf32_kernel<1><<<g, 256>>>(ao, out_w, out_b, out);
    }
}

// round 3
// speedup vs baseline: 3.5308x; 2.9841x over previous
#include <cuda_runtime.h>
#include <math.h>

#define BB 2
#define SS 2048
#define EE 1024
#define HH 16
#define DD 64
#define MM (BB*SS)

// Scratch (static device globals; no runtime allocation)
__device__ float g_q[BB*HH*SS*DD];      // 16 MB  [B,H,S,D]
__device__ float g_k[BB*HH*SS*DD];      // 16 MB
__device__ float g_v[BB*HH*SS*DD];      // 16 MB (pre-masked)
__device__ float g_vmean[BB*HH*DD];
__device__ float g_ao[BB*SS*EE];        // 16 MB, layout [B,S,H,D] == [B,S,E]
__device__ float g_active[HH];

// ---------------------------------------------------------------------------
// helpers
// ---------------------------------------------------------------------------
__device__ __forceinline__ unsigned f2tf32(float x) {
    unsigned r;
    asm("cvt.rna.tf32.f32 %0, %1;" : "=r"(r) : "f"(x));
    return r;
}
__device__ __forceinline__ float uaf(unsigned u) { return __uint_as_float(u); }

__device__ __forceinline__ void mma_tf32(float c[4], const unsigned a[4], const unsigned b[2]) {
    asm volatile(
        "mma.sync.aligned.m16n8k8.row.col.f32.tf32.tf32.f32 "
        "{%0,%1,%2,%3}, {%4,%5,%6,%7}, {%8,%9}, {%0,%1,%2,%3};"
        : "+f"(c[0]), "+f"(c[1]), "+f"(c[2]), "+f"(c[3])
        : "r"(a[0]), "r"(a[1]), "r"(a[2]), "r"(a[3]),
          "r"(b[0]), "r"(b[1]));
}

// ---------------------------------------------------------------------------
// Head mask
// ---------------------------------------------------------------------------
__global__ void mask_kernel(const float* __restrict__ gates,
                            const float* __restrict__ imp,
                            const float* __restrict__ thr) {
    int h = threadIdx.x;
    if (h < HH) {
        float z  = gates[h] * imp[h];
        float gs = 1.0f / (1.0f + expf(-z));
        g_active[h] = (gs > thr[0]) ? 1.0f : 0.0f;
    }
}

// ---------------------------------------------------------------------------
// Split-TF32 GEMM: C[m,n] = sum_k A[m,k]*B[n,k] + bias[n]
// BM=BN=128, BK=16, 256 threads (8 warps 2x4), warp tile 64x32.
// A always split (hi+lo). B split iff SB. Terms: Ah*Bh + Al*Bh (+ Ah*Bl).
// MODE 0: qkv scatter epilogue. MODE 1: row-major write.
// ---------------------------------------------------------------------------
template <int MODE, bool SB>
__global__ void __launch_bounds__(256, 2) gemm_split_kernel(
    const float* __restrict__ A,
    const float* __restrict__ B,
    const float* __restrict__ bias,
    float* __restrict__ Y) {
    __shared__ unsigned Ah[128][20];
    __shared__ unsigned Al[128][20];
    __shared__ unsigned Bh[128][20];
    __shared__ unsigned Bl[128][20];

    const int tid  = threadIdx.x;
    const int lane = tid & 31;
    const int warp = tid >> 5;
    const int wm = (warp >> 2) * 64;
    const int wn = (warp & 3) * 32;
    const int m0 = blockIdx.y * 128;
    const int n0 = blockIdx.x * 128;
    const int grp = lane >> 2;
    const int tig = lane & 3;

    const int grow = tid >> 1;          // 0..127
    const int gk   = (tid & 1) * 8;     // 0 or 8
    const float* Aptr = A + (size_t)(m0 + grow) * EE + gk;
    const float* Bptr = B + (size_t)(n0 + grow) * EE + gk;

    float acc[4][4][4];
#pragma unroll
    for (int i = 0; i < 4; i++)
#pragma unroll
        for (int j = 0; j < 4; j++)
#pragma unroll
            for (int r = 0; r < 4; r++) acc[i][j][r] = 0.f;

    float4 pa[2], pb[2];
#pragma unroll
    for (int i = 0; i < 2; i++) {
        pa[i] = *(const float4*)(Aptr + 4 * i);
        pb[i] = *(const float4*)(Bptr + 4 * i);
    }

    const int NT = EE / 16;  // 64 k-tiles
    for (int kt = 0; kt < NT; kt++) {
#pragma unroll
        for (int i = 0; i < 2; i++) {
            float av[4] = {pa[i].x, pa[i].y, pa[i].z, pa[i].w};
            float bv[4] = {pb[i].x, pb[i].y, pb[i].z, pb[i].w};
            uint4 ah, al, bh, bl;
            unsigned* ahp = &ah.x; unsigned* alp = &al.x;
            unsigned* bhp = &bh.x; unsigned* blp = &bl.x;
#pragma unroll
            for (int c = 0; c < 4; c++) {
                unsigned h = f2tf32(av[c]);
                ahp[c] = h; alp[c] = f2tf32(av[c] - uaf(h));
                unsigned hb = f2tf32(bv[c]);
                bhp[c] = hb; blp[c] = f2tf32(bv[c] - uaf(hb));
            }
            *(uint4*)&Ah[grow][gk + 4 * i] = ah;
            *(uint4*)&Al[grow][gk + 4 * i] = al;
            *(uint4*)&Bh[grow][gk + 4 * i] = bh;
            if (SB) *(uint4*)&Bl[grow][gk + 4 * i] = bl;
        }
        __syncthreads();

        if (kt + 1 < NT) {
            const float* An = Aptr + (kt + 1) * 16;
            const float* Bn = Bptr + (kt + 1) * 16;
#pragma unroll
            for (int i = 0; i < 2; i++) {
                pa[i] = *(const float4*)(An + 4 * i);
                pb[i] = *(const float4*)(Bn + 4 * i);
            }
        }

#pragma unroll
        for (int ks = 0; ks < 2; ks++) {
            const int kq = ks * 8 + tig;
            unsigned ah[4][4], al[4][4];
#pragma unroll
            for (int mi = 0; mi < 4; mi++) {
                const int mr = wm + mi * 16 + grp;
                ah[mi][0] = Ah[mr][kq];     ah[mi][1] = Ah[mr + 8][kq];
                ah[mi][2] = Ah[mr][kq + 4]; ah[mi][3] = Ah[mr + 8][kq + 4];
                al[mi][0] = Al[mr][kq];     al[mi][1] = Al[mr + 8][kq];
                al[mi][2] = Al[mr][kq + 4]; al[mi][3] = Al[mr + 8][kq + 4];
            }
            unsigned bh[4][2], bl[4][2];
#pragma unroll
            for (int ni = 0; ni < 4; ni++) {
                const int nr = wn + ni * 8 + grp;
                bh[ni][0] = Bh[nr][kq]; bh[ni][1] = Bh[nr][kq + 4];
                if (SB) { bl[ni][0] = Bl[nr][kq]; bl[ni][1] = Bl[nr][kq + 4]; }
            }
#pragma unroll
            for (int mi = 0; mi < 4; mi++)
#pragma unroll
                for (int ni = 0; ni < 4; ni++) {
                    mma_tf32(acc[mi][ni], ah[mi], bh[ni]);
                    mma_tf32(acc[mi][ni], al[mi], bh[ni]);
                    if (SB) mma_tf32(acc[mi][ni], ah[mi], bl[ni]);
                }
        }
        __syncthreads();
    }

    // epilogue
#pragma unroll
    for (int mi = 0; mi < 4; mi++) {
        const int rbase = m0 + wm + mi * 16 + grp;
#pragma unroll
        for (int ni = 0; ni < 4; ni++) {
            const int j = n0 + wn + ni * 8 + 2 * tig;
            const float b0 = bias[j], b1 = bias[j + 1];
#pragma unroll
            for (int rh = 0; rh < 2; rh++) {
                const int m = rbase + rh * 8;
                const float v0 = acc[mi][ni][rh * 2 + 0] + b0;
                const float v1 = acc[mi][ni][rh * 2 + 1] + b1;
                if (MODE == 1) {
                    float2 o; o.x = v0; o.y = v1;
                    *(float2*)(Y + (size_t)m * EE + j) = o;
                } else {
                    const int cc  = j >> 10;
                    const int rem = j & 1023;
                    const int h = rem >> 6, d = rem & 63;
                    const int bI = m >> 11;
                    const int s  = m & (SS - 1);
                    const size_t off = (((size_t)(bI * HH + h)) * SS + s) * DD + d;
                    float2 o;
                    if (cc == 0) {
                        o.x = v0; o.y = v1; *(float2*)(g_q + off) = o;
                    } else if (cc == 1) {
                        o.x = v0; o.y = v1; *(float2*)(g_k + off) = o;
                    } else {
                        const float am = g_active[h];
                        o.x = v0 * am; o.y = v1 * am; *(float2*)(g_v + off) = o;
                    }
                }
            }
        }
    }
}

// ---------------------------------------------------------------------------
// vmean[b,h,d] = mean_s v[b,h,s,d]
// ---------------------------------------------------------------------------
__global__ void vmean_kernel() {
    int bh = blockIdx.x;
    int d = threadIdx.x & 63;
    int chunk = threadIdx.x >> 6;
    size_t base = (size_t)bh * SS * DD;
    float sum = 0.f;
    for (int s = chunk * 512; s < (chunk + 1) * 512; s++)
        sum += g_v[base + (size_t)s * DD + d];
    __shared__ float red[256];
    red[threadIdx.x] = sum;
    __syncthreads();
    if (chunk == 0) {
        float t = red[d] + red[64 + d] + red[128 + d] + red[192 + d];
        g_vmean[bh * DD + d] = t * (1.0f / SS);
    }
}

// ---------------------------------------------------------------------------
// Tensor-core flash attention. BQ=128 (8 warps x m16), KV tile 64.
// QK: 2-term split-tf32 (Q split, K 1x). PV: 1-term tf32.
// Smem (dynamic, 70656B): Ks[64][68], Vs[64][72], Ps[128][68] (tf32 bits).
// ---------------------------------------------------------------------------
#define KSTR 68
#define VSTR 72
#define PSTR 68
#define SMEM_ATTN ((64*KSTR + 64*VSTR + 128*PSTR) * 4)

__global__ void __launch_bounds__(256, 1) attn_tc_kernel() {
    extern __shared__ unsigned sh[];
    unsigned* Ks = sh;
    unsigned* Vs = sh + 64 * KSTR;
    unsigned* Ps = sh + 64 * KSTR + 64 * VSTR;

    const int tid  = threadIdx.x;
    const int lane = tid & 31;
    const int warp = tid >> 5;
    const int grp  = lane >> 2;
    const int tig  = lane & 3;
    const int wr   = warp * 16;

    const int b = blockIdx.z, h = blockIdx.y;
    const int q0 = blockIdx.x * 128;
    const size_t bh = (size_t)(b * HH + h) * SS * DD;

    // Q fragments (split hi/lo), rows q0+wr+grp(+8), cols kt*8+tig(+4)
    unsigned qh[8][4], ql[8][4];
#pragma unroll
    for (int kt = 0; kt < 8; kt++) {
        const int r0 = q0 + wr + grp;
        const int c0 = kt * 8 + tig;
        float v0 = g_q[bh + (size_t)r0 * DD + c0];
        float v1 = g_q[bh + (size_t)(r0 + 8) * DD + c0];
        float v2 = g_q[bh + (size_t)r0 * DD + c0 + 4];
        float v3 = g_q[bh + (size_t)(r0 + 8) * DD + c0 + 4];
        qh[kt][0] = f2tf32(v0); ql[kt][0] = f2tf32(v0 - uaf(qh[kt][0]));
        qh[kt][1] = f2tf32(v1); ql[kt][1] = f2tf32(v1 - uaf(qh[kt][1]));
        qh[kt][2] = f2tf32(v2); ql[kt][2] = f2tf32(v2 - uaf(qh[kt][2]));
        qh[kt][3] = f2tf32(v3); ql[kt][3] = f2tf32(v3 - uaf(qh[kt][3]));
    }

    float o[8][4];
#pragma unroll
    for (int i = 0; i < 8; i++)
#pragma unroll
        for (int j = 0; j < 4; j++) o[i][j] = 0.f;
    float m0 = -1e30f, m1 = -1e30f, l0 = 0.f, l1 = 0.f;

    const int ldr = tid >> 2;          // 0..63 kv row for loads
    const int ldc = (tid & 3) * 16;    // col base

    for (int kv = 0; kv < SS; kv += 64) {
        __syncthreads();   // prior readers of Ks/Vs are done
        {
            const float4* kp = (const float4*)(g_k + bh + (size_t)(kv + ldr) * DD + ldc);
            const float4* vp = (const float4*)(g_v + bh + (size_t)(kv + ldr) * DD + ldc);
#pragma unroll
            for (int i = 0; i < 4; i++) {
                float4 kk = kp[i];
                float4 vv = vp[i];
                unsigned* kd = &Ks[ldr * KSTR + ldc + 4 * i];
                unsigned* vd = &Vs[ldr * VSTR + ldc + 4 * i];
                kd[0] = f2tf32(kk.x); kd[1] = f2tf32(kk.y);
                kd[2] = f2tf32(kk.z); kd[3] = f2tf32(kk.w);
                vd[0] = f2tf32(vv.x); vd[1] = f2tf32(vv.y);
                vd[2] = f2tf32(vv.z); vd[3] = f2tf32(vv.w);
            }
        }
        __syncthreads();

        // QK: scores c[nt][4] for 16 rows x 64 cols (2-term)
        float c[8][4];
#pragma unroll
        for (int i = 0; i < 8; i++)
#pragma unroll
            for (int j = 0; j < 4; j++) c[i][j] = 0.f;
#pragma unroll
        for (int ks = 0; ks < 8; ks++) {
#pragma unroll
            for (int nt = 0; nt < 8; nt++) {
                unsigned bb[2];
                bb[0] = Ks[(nt * 8 + grp) * KSTR + ks * 8 + tig];
                bb[1] = Ks[(nt * 8 + grp) * KSTR + ks * 8 + tig + 4];
                mma_tf32(c[nt], qh[ks], bb);
                mma_tf32(c[nt], ql[ks], bb);
            }
        }

        // online softmax over this tile
        float mx0 = c[0][0], mx1 = c[0][2];
#pragma unroll
        for (int nt = 0; nt < 8; nt++) {
            mx0 = fmaxf(mx0, fmaxf(c[nt][0], c[nt][1]));
            mx1 = fmaxf(mx1, fmaxf(c[nt][2], c[nt][3]));
        }
        mx0 = fmaxf(mx0, __shfl_xor_sync(0xffffffffu, mx0, 1));
        mx0 = fmaxf(mx0, __shfl_xor_sync(0xffffffffu, mx0, 2));
        mx1 = fmaxf(mx1, __shfl_xor_sync(0xffffffffu, mx1, 1));
        mx1 = fmaxf(mx1, __shfl_xor_sync(0xffffffffu, mx1, 2));
        float mn0 = fmaxf(m0, mx0);
        float mn1 = fmaxf(m1, mx1);
        float sc0 = __expf(m0 - mn0);
        float sc1 = __expf(m1 - mn1);
        m0 = mn0; m1 = mn1;
#pragma unroll
        for (int dt = 0; dt < 8; dt++) {
            o[dt][0] *= sc0; o[dt][1] *= sc0;
            o[dt][2] *= sc1; o[dt][3] *= sc1;
        }
        float s0 = 0.f, s1 = 0.f;
#pragma unroll
        for (int nt = 0; nt < 8; nt++) {
            float p00 = __expf(c[nt][0] - m0);
            float p01 = __expf(c[nt][1] - m0);
            float p10 = __expf(c[nt][2] - m1);
            float p11 = __expf(c[nt][3] - m1);
            s0 += p00 + p01;
            s1 += p10 + p11;
            unsigned* pr0 = &Ps[(wr + grp) * PSTR + nt * 8 + 2 * tig];
            unsigned* pr1 = &Ps[(wr + grp + 8) * PSTR + nt * 8 + 2 * tig];
            pr0[0] = f2tf32(p00); pr0[1] = f2tf32(p01);
            pr1[0] = f2tf32(p10); pr1[1] = f2tf32(p11);
        }
        s0 += __shfl_xor_sync(0xffffffffu, s0, 1);
        s0 += __shfl_xor_sync(0xffffffffu, s0, 2);
        s1 += __shfl_xor_sync(0xffffffffu, s1, 1);
        s1 += __shfl_xor_sync(0xffffffffu, s1, 2);
        l0 = l0 * sc0 + s0;
        l1 = l1 * sc1 + s1;
        __syncwarp();   // P rows are warp-private; make writes visible in-warp

        // PV: o[dt] += P[16 x 64] @ V[64 x 64]
#pragma unroll
        for (int ks = 0; ks < 8; ks++) {
            unsigned aa[4];
            aa[0] = Ps[(wr + grp) * PSTR + ks * 8 + tig];
            aa[1] = Ps[(wr + grp + 8) * PSTR + ks * 8 + tig];
            aa[2] = Ps[(wr + grp) * PSTR + ks * 8 + tig + 4];
            aa[3] = Ps[(wr + grp + 8) * PSTR + ks * 8 + tig + 4];
#pragma unroll
            for (int dt = 0; dt < 8; dt++) {
                unsigned bb[2];
                bb[0] = Vs[(ks * 8 + tig) * VSTR + dt * 8 + grp];
                bb[1] = Vs[(ks * 8 + tig + 4) * VSTR + dt * 8 + grp];
                mma_tf32(o[dt], aa, bb);
            }
        }
    }

    // epilogue: normalize, add vmean, write [B,S,H,D]
    const float inv0 = 1.0f / l0;
    const float inv1 = 1.0f / l1;
    const int r0 = q0 + wr + grp;
    const size_t ob0 = ((size_t)(b * SS + r0) * HH + h) * DD;
    const size_t ob1 = ((size_t)(b * SS + r0 + 8) * HH + h) * DD;
    const float* vm = g_vmean + (size_t)(b * HH + h) * DD;
#pragma unroll
    for (int dt = 0; dt < 8; dt++) {
        const int col = dt * 8 + 2 * tig;
        const float v0 = vm[col], v1 = vm[col + 1];
        float2 w0, w1;
        w0.x = o[dt][0] * inv0 + v0; w0.y = o[dt][1] * inv0 + v1;
        w1.x = o[dt][2] * inv1 + v0; w1.y = o[dt][3] * inv1 + v1;
        *(float2*)(g_ao + ob0 + col) = w0;
        *(float2*)(g_ao + ob1 + col) = w1;
    }
}

// ---------------------------------------------------------------------------
extern "C" void kernel_launch(void* const* d_in, const int* in_sizes, int n_in,
                              void* d_out, int out_size) {
    const float* x      = (const float*)d_in[0];
    const float* qkv_w  = (const float*)d_in[1];
    const float* qkv_b  = (const float*)d_in[2];
    const float* out_w  = (const float*)d_in[3];
    const float* out_b  = (const float*)d_in[4];
    const float* gates  = (const float*)d_in[5];
    const float* imp    = (const float*)d_in[6];
    const float* thr    = (const float*)d_in[7];
    float* out = (float*)d_out;

    static bool attr_set = false;
    if (!attr_set) {
        cudaFuncSetAttribute(attn_tc_kernel,
                             cudaFuncAttributeMaxDynamicSharedMemorySize, SMEM_ATTN);
        attr_set = true;
    }

    mask_kernel<<<1, 32>>>(gates, imp, thr);

    // QKV projection (3-term split tf32)
    {
        dim3 g(3 * EE / 128, MM / 128);      // 24 x 32
        gemm_split_kernel<0, true><<<g, 256>>>(x, qkv_w, qkv_b, nullptr);
    }

    vmean_kernel<<<BB * HH, 256>>>();

    // Attention (tensor cores)
    {
        dim3 g(SS / 128, HH, BB);            // 16 x 16 x 2
        attn_tc_kernel<<<g, 256, SMEM_ATTN>>>();
    }

    // Output projection (2-term split tf32)
    {
        float* ao;
        cudaGetSymbolAddress((void**)&ao, g_ao);
        dim3 g(EE / 128, MM / 128);          // 8 x 32
        gemm_split_kernel<1, false><<<g, 256>>>(ao, out_w, out_b, out);
    }
}

// round 4
// speedup vs baseline: 6.2011x; 1.7563x over previous
#include <cuda_runtime.h>
#include <math.h>

#define BB 2
#define SS 2048
#define EE 1024
#define HH 16
#define DD 64
#define MM (BB*SS)

// Scratch (static device globals; no runtime allocation)
__device__ float g_q[BB*HH*SS*DD];      // 16 MB  [B,H,S,D]
__device__ float g_k[BB*HH*SS*DD];      // 16 MB
__device__ float g_v[BB*HH*SS*DD];      // 16 MB (pre-masked)
__device__ float g_vmean[BB*HH*DD];
__device__ float g_ao[BB*SS*EE];        // 16 MB, layout [B,S,H,D] == [B,S,E]
__device__ float g_active[HH];

// ---------------------------------------------------------------------------
// helpers
// ---------------------------------------------------------------------------
__device__ __forceinline__ unsigned f2tf32(float x) {
    unsigned r;
    asm("cvt.rna.tf32.f32 %0, %1;" : "=r"(r) : "f"(x));
    return r;
}
__device__ __forceinline__ float uaf(unsigned u) { return __uint_as_float(u); }

__device__ __forceinline__ void mma_tf32(float c[4], const unsigned a[4], const unsigned b[2]) {
    asm volatile(
        "mma.sync.aligned.m16n8k8.row.col.f32.tf32.tf32.f32 "
        "{%0,%1,%2,%3}, {%4,%5,%6,%7}, {%8,%9}, {%0,%1,%2,%3};"
        : "+f"(c[0]), "+f"(c[1]), "+f"(c[2]), "+f"(c[3])
        : "r"(a[0]), "r"(a[1]), "r"(a[2]), "r"(a[3]),
          "r"(b[0]), "r"(b[1]));
}

__device__ __forceinline__ void cp16(unsigned dst, const void* src) {
    asm volatile("cp.async.cg.shared.global [%0], [%1], 16;\n" :: "r"(dst), "l"(src));
}
__device__ __forceinline__ void cp_commit() {
    asm volatile("cp.async.commit_group;\n");
}
__device__ __forceinline__ void cp_wait1() {
    asm volatile("cp.async.wait_group 1;\n");
}

// ---------------------------------------------------------------------------
// Head mask
// ---------------------------------------------------------------------------
__global__ void mask_kernel(const float* __restrict__ gates,
                            const float* __restrict__ imp,
                            const float* __restrict__ thr) {
    int h = threadIdx.x;
    if (h < HH) {
        float z  = gates[h] * imp[h];
        float gs = 1.0f / (1.0f + expf(-z));
        g_active[h] = (gs > thr[0]) ? 1.0f : 0.0f;
    }
}

// ---------------------------------------------------------------------------
// Split-TF32 GEMM: C[m,n] = sum_k A[m,k]*B[n,k] + bias[n]
// BM=BN=128, BK=16, 256 threads (8 warps 2x4), warp tile 64x32.
// A always split (hi+lo). B split iff SB. Terms: Ah*Bh + Al*Bh (+ Ah*Bl).
// MODE 0: qkv scatter epilogue (+ inactive-head block skip). MODE 1: row-major.
// ---------------------------------------------------------------------------
template <int MODE, bool SB>
__global__ void __launch_bounds__(256, 2) gemm_split_kernel(
    const float* __restrict__ A,
    const float* __restrict__ B,
    const float* __restrict__ bias,
    float* __restrict__ Y) {
    __shared__ unsigned Ah[128][20];
    __shared__ unsigned Al[128][20];
    __shared__ unsigned Bh[128][20];
    __shared__ unsigned Bl[128][20];

    const int m0 = blockIdx.y * 128;
    const int n0 = blockIdx.x * 128;

    if (MODE == 0) {
        // this block covers exactly 2 heads of one of q/k/v; skip if both inactive
        const int hA = (n0 & 1023) >> 6;
        if (g_active[hA] == 0.0f && g_active[hA + 1] == 0.0f) return;
    }

    const int tid  = threadIdx.x;
    const int lane = tid & 31;
    const int warp = tid >> 5;
    const int wm = (warp >> 2) * 64;
    const int wn = (warp & 3) * 32;
    const int grp = lane >> 2;
    const int tig = lane & 3;

    const int grow = tid >> 1;          // 0..127
    const int gk   = (tid & 1) * 8;     // 0 or 8
    const float* Aptr = A + (size_t)(m0 + grow) * EE + gk;
    const float* Bptr = B + (size_t)(n0 + grow) * EE + gk;

    float acc[4][4][4];
#pragma unroll
    for (int i = 0; i < 4; i++)
#pragma unroll
        for (int j = 0; j < 4; j++)
#pragma unroll
            for (int r = 0; r < 4; r++) acc[i][j][r] = 0.f;

    float4 pa[2], pb[2];
#pragma unroll
    for (int i = 0; i < 2; i++) {
        pa[i] = *(const float4*)(Aptr + 4 * i);
        pb[i] = *(const float4*)(Bptr + 4 * i);
    }

    const int NT = EE / 16;  // 64 k-tiles
    for (int kt = 0; kt < NT; kt++) {
#pragma unroll
        for (int i = 0; i < 2; i++) {
            float av[4] = {pa[i].x, pa[i].y, pa[i].z, pa[i].w};
            float bv[4] = {pb[i].x, pb[i].y, pb[i].z, pb[i].w};
            uint4 ah, al, bh, bl;
            unsigned* ahp = &ah.x; unsigned* alp = &al.x;
            unsigned* bhp = &bh.x; unsigned* blp = &bl.x;
#pragma unroll
            for (int c = 0; c < 4; c++) {
                unsigned h = f2tf32(av[c]);
                ahp[c] = h; alp[c] = f2tf32(av[c] - uaf(h));
                unsigned hb = f2tf32(bv[c]);
                bhp[c] = hb; blp[c] = f2tf32(bv[c] - uaf(hb));
            }
            *(uint4*)&Ah[grow][gk + 4 * i] = ah;
            *(uint4*)&Al[grow][gk + 4 * i] = al;
            *(uint4*)&Bh[grow][gk + 4 * i] = bh;
            if (SB) *(uint4*)&Bl[grow][gk + 4 * i] = bl;
        }
        __syncthreads();

        if (kt + 1 < NT) {
            const float* An = Aptr + (kt + 1) * 16;
            const float* Bn = Bptr + (kt + 1) * 16;
#pragma unroll
            for (int i = 0; i < 2; i++) {
                pa[i] = *(const float4*)(An + 4 * i);
                pb[i] = *(const float4*)(Bn + 4 * i);
            }
        }

#pragma unroll
        for (int ks = 0; ks < 2; ks++) {
            const int kq = ks * 8 + tig;
            unsigned ah[4][4], al[4][4];
#pragma unroll
            for (int mi = 0; mi < 4; mi++) {
                const int mr = wm + mi * 16 + grp;
                ah[mi][0] = Ah[mr][kq];     ah[mi][1] = Ah[mr + 8][kq];
                ah[mi][2] = Ah[mr][kq + 4]; ah[mi][3] = Ah[mr + 8][kq + 4];
                al[mi][0] = Al[mr][kq];     al[mi][1] = Al[mr + 8][kq];
                al[mi][2] = Al[mr][kq + 4]; al[mi][3] = Al[mr + 8][kq + 4];
            }
            unsigned bh[4][2], bl[4][2];
#pragma unroll
            for (int ni = 0; ni < 4; ni++) {
                const int nr = wn + ni * 8 + grp;
                bh[ni][0] = Bh[nr][kq]; bh[ni][1] = Bh[nr][kq + 4];
                if (SB) { bl[ni][0] = Bl[nr][kq]; bl[ni][1] = Bl[nr][kq + 4]; }
            }
#pragma unroll
            for (int mi = 0; mi < 4; mi++)
#pragma unroll
                for (int ni = 0; ni < 4; ni++) {
                    mma_tf32(acc[mi][ni], ah[mi], bh[ni]);
                    mma_tf32(acc[mi][ni], al[mi], bh[ni]);
                    if (SB) mma_tf32(acc[mi][ni], ah[mi], bl[ni]);
                }
        }
        __syncthreads();
    }

    // epilogue
#pragma unroll
    for (int mi = 0; mi < 4; mi++) {
        const int rbase = m0 + wm + mi * 16 + grp;
#pragma unroll
        for (int ni = 0; ni < 4; ni++) {
            const int j = n0 + wn + ni * 8 + 2 * tig;
            const float b0 = bias[j], b1 = bias[j + 1];
#pragma unroll
            for (int rh = 0; rh < 2; rh++) {
                const int m = rbase + rh * 8;
                const float v0 = acc[mi][ni][rh * 2 + 0] + b0;
                const float v1 = acc[mi][ni][rh * 2 + 1] + b1;
                if (MODE == 1) {
                    float2 o; o.x = v0; o.y = v1;
                    *(float2*)(Y + (size_t)m * EE + j) = o;
                } else {
                    const int cc  = j >> 10;
                    const int rem = j & 1023;
                    const int h = rem >> 6, d = rem & 63;
                    const int bI = m >> 11;
                    const int s  = m & (SS - 1);
                    const size_t off = (((size_t)(bI * HH + h)) * SS + s) * DD + d;
                    float2 o;
                    if (cc == 0) {
                        o.x = v0; o.y = v1; *(float2*)(g_q + off) = o;
                    } else if (cc == 1) {
                        o.x = v0; o.y = v1; *(float2*)(g_k + off) = o;
                    } else {
                        const float am = g_active[h];
                        o.x = v0 * am; o.y = v1 * am; *(float2*)(g_v + off) = o;
                    }
                }
            }
        }
    }
}

// ---------------------------------------------------------------------------
// vmean[b,h,d] = mean_s v[b,h,s,d]  (float4 loads, skip inactive heads)
// ---------------------------------------------------------------------------
__global__ void vmean_kernel() {
    const int bh = blockIdx.x;           // 0..BB*HH-1
    if (g_active[bh & (HH - 1)] == 0.0f) return;
    const int d4    = (threadIdx.x & 15) * 4;
    const int chunk = threadIdx.x >> 4;  // 0..15, 128 s each
    const size_t base = (size_t)bh * SS * DD;
    float4 sum = {0.f, 0.f, 0.f, 0.f};
    for (int s = chunk * 128; s < (chunk + 1) * 128; s++) {
        float4 t = *(const float4*)(g_v + base + (size_t)s * DD + d4);
        sum.x += t.x; sum.y += t.y; sum.z += t.z; sum.w += t.w;
    }
    __shared__ float4 red[256];
    red[threadIdx.x] = sum;
    __syncthreads();
    if (chunk == 0) {
        float4 t = {0.f, 0.f, 0.f, 0.f};
#pragma unroll
        for (int c = 0; c < 16; c++) {
            float4 r = red[c * 16 + (threadIdx.x & 15)];
            t.x += r.x; t.y += r.y; t.z += r.z; t.w += r.w;
        }
        const float inv = 1.0f / SS;
        t.x *= inv; t.y *= inv; t.z *= inv; t.w *= inv;
        *(float4*)(g_vmean + bh * DD + d4) = t;
    }
}

// ---------------------------------------------------------------------------
// Tensor-core flash attention, v2:
//  - cp.async double-buffered K/V tiles (raw fp32 in smem, cvt at frag read)
//  - P kept entirely in registers via k-slot permutation sigma(j)=2j / 2(j-4)+1
//    (A-frag = own QK accum regs; V B-frag reads rows 2tig, 2tig+1)
//  - inactive heads: write zeros, exit
// BQ=128 (8 warps x m16), KV tile 64. QK 2-term split, PV 1-term.
// ---------------------------------------------------------------------------
#define KSTR 68
#define VSTR 68
#define TKW  (64 * KSTR)              // words per K tile
#define TVW  (64 * VSTR)
#define BUFW (TKW + TVW)              // words per buffer
#define SMEM_ATTN (2 * BUFW * 4)      // 69632 B

__global__ void __launch_bounds__(256, 1) attn_tc_kernel() {
    extern __shared__ float sh[];

    const int tid  = threadIdx.x;
    const int lane = tid & 31;
    const int warp = tid >> 5;
    const int grp  = lane >> 2;
    const int tig  = lane & 3;
    const int wr   = warp * 16;

    const int b = blockIdx.z, h = blockIdx.y;
    const int q0 = blockIdx.x * 128;
    const size_t bh = (size_t)(b * HH + h) * SS * DD;

    if (g_active[h] == 0.0f) {
        // attention output for a masked head is exactly zero (v==0, vmean==0)
        const float4 z = {0.f, 0.f, 0.f, 0.f};
        for (int i = tid; i < 128 * 16; i += 256) {
            const int r = i >> 4, c = (i & 15) * 4;
            *(float4*)(g_ao + ((size_t)(b * SS + q0 + r) * HH + h) * DD + c) = z;
        }
        return;
    }

    const unsigned sbase = (unsigned)__cvta_generic_to_shared(sh);
    const int ldr = tid >> 2;          // 0..63 kv row for loads
    const int ldc = (tid & 3) * 16;    // col base (floats)

    // Q fragments (split hi/lo)
    unsigned qh[8][4], ql[8][4];
#pragma unroll
    for (int kt = 0; kt < 8; kt++) {
        const int r0 = q0 + wr + grp;
        const int c0 = kt * 8 + tig;
        float v0 = g_q[bh + (size_t)r0 * DD + c0];
        float v1 = g_q[bh + (size_t)(r0 + 8) * DD + c0];
        float v2 = g_q[bh + (size_t)r0 * DD + c0 + 4];
        float v3 = g_q[bh + (size_t)(r0 + 8) * DD + c0 + 4];
        qh[kt][0] = f2tf32(v0); ql[kt][0] = f2tf32(v0 - uaf(qh[kt][0]));
        qh[kt][1] = f2tf32(v1); ql[kt][1] = f2tf32(v1 - uaf(qh[kt][1]));
        qh[kt][2] = f2tf32(v2); ql[kt][2] = f2tf32(v2 - uaf(qh[kt][2]));
        qh[kt][3] = f2tf32(v3); ql[kt][3] = f2tf32(v3 - uaf(qh[kt][3]));
    }

    float o[8][4];
#pragma unroll
    for (int i = 0; i < 8; i++)
#pragma unroll
        for (int j = 0; j < 4; j++) o[i][j] = 0.f;
    float m0 = -1e30f, m1 = -1e30f, l0 = 0.f, l1 = 0.f;

    // async tile loader: K tile + V tile into buffer `buf`
    auto issue_tile = [&](int kvt, int buf) {
        const float* kp = g_k + bh + (size_t)(kvt * 64 + ldr) * DD + ldc;
        const float* vp = g_v + bh + (size_t)(kvt * 64 + ldr) * DD + ldc;
        const unsigned kd = sbase + (buf * BUFW + ldr * KSTR + ldc) * 4;
        const unsigned vd = sbase + (buf * BUFW + TKW + ldr * VSTR + ldc) * 4;
#pragma unroll
        for (int c = 0; c < 4; c++) {
            cp16(kd + 16 * c, kp + 4 * c);
            cp16(vd + 16 * c, vp + 4 * c);
        }
    };

    issue_tile(0, 0);
    cp_commit();

    const int NTILE = SS / 64;  // 32
    for (int t = 0; t < NTILE; t++) {
        const int buf = t & 1;
        if (t + 1 < NTILE) issue_tile(t + 1, buf ^ 1);
        cp_commit();            // empty group on last iter keeps count uniform
        cp_wait1();
        __syncthreads();

        const float* Kf = sh + buf * BUFW;
        const float* Vf = Kf + TKW;

        // ---- QK: c[nt][4], 2-term split ----
        float c[8][4];
#pragma unroll
        for (int i = 0; i < 8; i++)
#pragma unroll
            for (int j = 0; j < 4; j++) c[i][j] = 0.f;
#pragma unroll
        for (int ks = 0; ks < 8; ks++) {
            const int kq = ks * 8 + tig;
#pragma unroll
            for (int nt = 0; nt < 8; nt++) {
                unsigned bb[2];
                bb[0] = f2tf32(Kf[(nt * 8 + grp) * KSTR + kq]);
                bb[1] = f2tf32(Kf[(nt * 8 + grp) * KSTR + kq + 4]);
                mma_tf32(c[nt], qh[ks], bb);
                mma_tf32(c[nt], ql[ks], bb);
            }
        }

        // ---- online softmax -> P in registers ----
        float mx0 = c[0][0], mx1 = c[0][2];
#pragma unroll
        for (int nt = 0; nt < 8; nt++) {
            mx0 = fmaxf(mx0, fmaxf(c[nt][0], c[nt][1]));
            mx1 = fmaxf(mx1, fmaxf(c[nt][2], c[nt][3]));
        }
        mx0 = fmaxf(mx0, __shfl_xor_sync(0xffffffffu, mx0, 1));
        mx0 = fmaxf(mx0, __shfl_xor_sync(0xffffffffu, mx0, 2));
        mx1 = fmaxf(mx1, __shfl_xor_sync(0xffffffffu, mx1, 1));
        mx1 = fmaxf(mx1, __shfl_xor_sync(0xffffffffu, mx1, 2));
        const float mn0 = fmaxf(m0, mx0);
        const float mn1 = fmaxf(m1, mx1);
        const float sc0 = __expf(m0 - mn0);
        const float sc1 = __expf(m1 - mn1);
        m0 = mn0; m1 = mn1;
#pragma unroll
        for (int dt = 0; dt < 8; dt++) {
            o[dt][0] *= sc0; o[dt][1] *= sc0;
            o[dt][2] *= sc1; o[dt][3] *= sc1;
        }
        unsigned pu[8][4];
        float s0 = 0.f, s1 = 0.f;
#pragma unroll
        for (int nt = 0; nt < 8; nt++) {
            const float p00 = __expf(c[nt][0] - m0);
            const float p01 = __expf(c[nt][1] - m0);
            const float p10 = __expf(c[nt][2] - m1);
            const float p11 = __expf(c[nt][3] - m1);
            s0 += p00 + p01;
            s1 += p10 + p11;
            pu[nt][0] = f2tf32(p00); pu[nt][1] = f2tf32(p01);
            pu[nt][2] = f2tf32(p10); pu[nt][3] = f2tf32(p11);
        }
        s0 += __shfl_xor_sync(0xffffffffu, s0, 1);
        s0 += __shfl_xor_sync(0xffffffffu, s0, 2);
        s1 += __shfl_xor_sync(0xffffffffu, s1, 1);
        s1 += __shfl_xor_sync(0xffffffffu, s1, 2);
        l0 = l0 * sc0 + s0;
        l1 = l1 * sc1 + s1;

        // ---- PV with permuted k-slots: sigma(tig)=2tig, sigma(tig+4)=2tig+1 ----
        // A-frag = {P[grp][2tig], P[grp+8][2tig], P[grp][2tig+1], P[grp+8][2tig+1]}
        //        = {pu[ks][0], pu[ks][2], pu[ks][1], pu[ks][3]}   (own registers!)
        // B-frag = V rows ks*8+2tig, ks*8+2tig+1 (bank-conflict-free at VSTR=68)
#pragma unroll
        for (int ks = 0; ks < 8; ks++) {
            unsigned aa[4] = {pu[ks][0], pu[ks][2], pu[ks][1], pu[ks][3]};
            const int vr0 = (ks * 8 + 2 * tig) * VSTR;
#pragma unroll
            for (int dt = 0; dt < 8; dt++) {
                unsigned bb[2];
                bb[0] = f2tf32(Vf[vr0 + dt * 8 + grp]);
                bb[1] = f2tf32(Vf[vr0 + VSTR + dt * 8 + grp]);
                mma_tf32(o[dt], aa, bb);
            }
        }
        __syncthreads();   // all warps done with buf before it's refilled
    }

    // epilogue: normalize, add vmean, write [B,S,H,D]
    const float inv0 = 1.0f / l0;
    const float inv1 = 1.0f / l1;
    const int r0 = q0 + wr + grp;
    const size_t ob0 = ((size_t)(b * SS + r0) * HH + h) * DD;
    const size_t ob1 = ((size_t)(b * SS + r0 + 8) * HH + h) * DD;
    const float* vm = g_vmean + (size_t)(b * HH + h) * DD;
#pragma unroll
    for (int dt = 0; dt < 8; dt++) {
        const int col = dt * 8 + 2 * tig;
        const float v0 = vm[col], v1 = vm[col + 1];
        float2 w0, w1;
        w0.x = o[dt][0] * inv0 + v0; w0.y = o[dt][1] * inv0 + v1;
        w1.x = o[dt][2] * inv1 + v0; w1.y = o[dt][3] * inv1 + v1;
        *(float2*)(g_ao + ob0 + col) = w0;
        *(float2*)(g_ao + ob1 + col) = w1;
    }
}

// ---------------------------------------------------------------------------
extern "C" void kernel_launch(void* const* d_in, const int* in_sizes, int n_in,
                              void* d_out, int out_size) {
    const float* x      = (const float*)d_in[0];
    const float* qkv_w  = (const float*)d_in[1];
    const float* qkv_b  = (const float*)d_in[2];
    const float* out_w  = (const float*)d_in[3];
    const float* out_b  = (const float*)d_in[4];
    const float* gates  = (const float*)d_in[5];
    const float* imp    = (const float*)d_in[6];
    const float* thr    = (const float*)d_in[7];
    float* out = (float*)d_out;

    static bool attr_set = false;
    if (!attr_set) {
        cudaFuncSetAttribute(attn_tc_kernel,
                             cudaFuncAttributeMaxDynamicSharedMemorySize, SMEM_ATTN);
        attr_set = true;
    }

    mask_kernel<<<1, 32>>>(gates, imp, thr);

    // QKV projection (3-term split tf32)
    {
        dim3 g(3 * EE / 128, MM / 128);      // 24 x 32
        gemm_split_kernel<0, true><<<g, 256>>>(x, qkv_w, qkv_b, nullptr);
    }

    vmean_kernel<<<BB * HH, 256>>>();

    // Attention (tensor cores, double-buffered)
    {
        dim3 g(SS / 128, HH, BB);            // 16 x 16 x 2
        attn_tc_kernel<<<g, 256, SMEM_ATTN>>>();
    }

    // Output projection (2-term split tf32)
    {
        float* ao;
        cudaGetSymbolAddress((void**)&ao, g_ao);
        dim3 g(EE / 128, MM / 128);          // 8 x 32
        gemm_split_kernel<1, false><<<g, 256>>>(ao, out_w, out_b, out);
    }
}